// round 6
// baseline (speedup 1.0000x reference)
#include <cuda_runtime.h>
#include <cuda_bf16.h>
#include <cstdint>

#define NN 50000
#define NE 800000
#define NG 512
#define DD 64
#define DOUT 32
#define LN_EPS 1e-5f
#define SCAN_B 256
#define SCAN_GRID ((NN + SCAN_B - 1) / SCAN_B)   // 196

// ---------------- scratch (static device globals; 16B aligned) --------------
__device__ int g_is64;                          // 1 if index inputs are int64
__device__ __align__(16) int   g_edeg[NN];      // edge in-degree (no self loop)
__device__ __align__(16) float g_dinv[NN];
__device__ __align__(16) int   g_src[NE];
__device__ __align__(16) int   g_dst[NE];
__device__ __align__(16) int   g_rows[NN];      // per-block exclusive scan
__device__ __align__(16) int   g_bsum[SCAN_B];
__device__ __align__(16) int   g_bscan[SCAN_B];
__device__ __align__(16) int   g_rowstart[NN];  // CSR row offsets
__device__ __align__(16) int   g_cursor[NN];
__device__ __align__(16) int   g_csrc[NE];      // CSR: source node per slot
__device__ __align__(16) float g_cw[NE];        // CSR: edge weight per slot
__device__ __align__(16) float g_h[NN * DD];    // layer activations
__device__ __align__(16) float g_hw[NN * DD];   // h @ W
__device__ __align__(16) float g_pool[NG * DD];
__device__ __align__(16) float g_cnt[NG];

// ---------------- helpers ---------------------------------------------------
__device__ __forceinline__ float warp_sum(float v) {
    #pragma unroll
    for (int o = 16; o > 0; o >>= 1) v += __shfl_xor_sync(0xffffffffu, v, o);
    return v;
}
__device__ __forceinline__ int clampi(int v, int hi) {   // [0, hi)
    return v < 0 ? 0 : (v >= hi ? hi - 1 : v);
}
// read index i from a buffer that is either int64 or int32
__device__ __forceinline__ int read_idx(const void* p, int i) {
    if (g_is64) return (int)((const long long*)p)[i];
    return ((const int*)p)[i];
}

// ---------------- dtype probe ------------------------------------------------
// If buffer is int64 (values < 2^31), odd int32 words are all zero.
// Reads words [0, 512): <= 2KB, in-bounds under either dtype.
__global__ void k_detect(const int* __restrict__ raw) {
    __shared__ int any;
    if (threadIdx.x == 0) any = 0;
    __syncthreads();
    int w = 2 * threadIdx.x + 1;   // odd words 1..511
    if (raw[w] != 0) atomicOr(&any, 1);
    __syncthreads();
    if (threadIdx.x == 0) g_is64 = (any == 0) ? 1 : 0;
}

// ---------------- setup kernels ---------------------------------------------
__global__ void k_prep() {
    int i = blockIdx.x * blockDim.x + threadIdx.x;
    if (i < NN) g_edeg[i] = 0;
    if (i < NG * DD) g_pool[i] = 0.0f;
    if (i < NG) g_cnt[i] = 0.0f;
}

__global__ void k_deg(const void* __restrict__ ei) {
    int e = blockIdx.x * blockDim.x + threadIdx.x;
    if (e >= NE) return;
    int s = clampi(read_idx(ei, e), NN);
    int d = clampi(read_idx(ei, NE + e), NN);
    g_src[e] = s;
    g_dst[e] = d;
    atomicAdd(&g_edeg[d], 1);
}

__global__ void k_dinv() {
    int i = blockIdx.x * blockDim.x + threadIdx.x;
    if (i < NN) g_dinv[i] = rsqrtf((float)(g_edeg[i] + 1));  // +1 self loop
}

// exclusive scan of g_edeg -> g_rowstart (3 stages)
__global__ void k_scan1() {
    __shared__ int sh[SCAN_B];
    int t = threadIdx.x;
    int i = blockIdx.x * SCAN_B + t;
    int v = (i < NN) ? g_edeg[i] : 0;
    sh[t] = v;
    __syncthreads();
    #pragma unroll
    for (int off = 1; off < SCAN_B; off <<= 1) {
        int x = (t >= off) ? sh[t - off] : 0;
        __syncthreads();
        sh[t] += x;
        __syncthreads();
    }
    if (i < NN) g_rows[i] = sh[t] - v;            // exclusive within block
    if (t == SCAN_B - 1) g_bsum[blockIdx.x] = sh[t];
}

__global__ void k_scan2() {   // one block of SCAN_B threads
    __shared__ int sh[SCAN_B];
    int t = threadIdx.x;
    int v = (t < SCAN_GRID) ? g_bsum[t] : 0;
    sh[t] = v;
    __syncthreads();
    #pragma unroll
    for (int off = 1; off < SCAN_B; off <<= 1) {
        int x = (t >= off) ? sh[t - off] : 0;
        __syncthreads();
        sh[t] += x;
        __syncthreads();
    }
    g_bscan[t] = sh[t] - v;
}

__global__ void k_scan3() {
    int i = blockIdx.x * blockDim.x + threadIdx.x;
    if (i >= NN) return;
    int r = g_rows[i] + g_bscan[i >> 8];
    g_rowstart[i] = r;
    g_cursor[i] = r;
}

__global__ void k_bucket() {
    int e = blockIdx.x * blockDim.x + threadIdx.x;
    if (e >= NE) return;
    int s = g_src[e];
    int d = g_dst[e];
    float w = g_dinv[s] * g_dinv[d];
    int pos = atomicAdd(&g_cursor[d], 1);
    g_csrc[pos] = s;
    g_cw[pos] = w;
}

__global__ void k_cnt(const void* __restrict__ batch) {
    int i = blockIdx.x * blockDim.x + threadIdx.x;
    if (i < NN) atomicAdd(&g_cnt[clampi(read_idx(batch, i), NG)], 1.0f);
}

// ---------------- GEMM: g_hw = in @ W  (Nx64 @ 64x64) -----------------------
// 256 threads, 32 rows/block, each thread 2 rows x 4 cols.
__global__ void k_matmul(int use_h, const float* __restrict__ xin,
                         const float* __restrict__ W) {
    __shared__ float Ws[DD * DD];
    __shared__ float Is[32][DD + 1];
    const float* in = use_h ? g_h : xin;

    int t = threadIdx.x;
    int base = blockIdx.x * 32;

    #pragma unroll
    for (int r = 0; r < 16; r++) Ws[t + 256 * r] = W[t + 256 * r];
    #pragma unroll
    for (int r = 0; r < 8; r++) {
        int idx = t + 256 * r;
        int row = idx >> 6, col = idx & 63;
        int grow = base + row;
        Is[row][col] = (grow < NN) ? in[grow * DD + col] : 0.0f;
    }
    __syncthreads();

    int rg = t >> 4, cg = t & 15;
    int r0 = rg * 2, r1 = r0 + 1;
    int j0 = cg * 4;

    float4 acc0 = make_float4(0.f, 0.f, 0.f, 0.f);
    float4 acc1 = make_float4(0.f, 0.f, 0.f, 0.f);
    #pragma unroll
    for (int k = 0; k < DD; k++) {
        float4 w4 = *reinterpret_cast<const float4*>(&Ws[k * DD + j0]);
        float a0 = Is[r0][k];
        float a1 = Is[r1][k];
        acc0.x += a0 * w4.x; acc0.y += a0 * w4.y; acc0.z += a0 * w4.z; acc0.w += a0 * w4.w;
        acc1.x += a1 * w4.x; acc1.y += a1 * w4.y; acc1.z += a1 * w4.z; acc1.w += a1 * w4.w;
    }
    int grow0 = base + r0, grow1 = base + r1;
    if (grow0 < NN) *reinterpret_cast<float4*>(&g_hw[grow0 * DD + j0]) = acc0;
    if (grow1 < NN) *reinterpret_cast<float4*>(&g_hw[grow1 * DD + j0]) = acc1;
}

// ---------------- fused gather + bias + LN + ReLU (+ pool on last) ----------
// one warp per node; lane handles cols lane and lane+32.
__global__ void k_gather_ln(const float* __restrict__ b,
                            const float* __restrict__ lw,
                            const float* __restrict__ lb,
                            int last, const void* __restrict__ batch) {
    int n = (blockIdx.x * blockDim.x + threadIdx.x) >> 5;
    int lane = threadIdx.x & 31;
    if (n >= NN) return;

    float ws = g_dinv[n]; ws *= ws;
    float a0 = b[lane]      + ws * g_hw[n * DD + lane];
    float a1 = b[lane + 32] + ws * g_hw[n * DD + lane + 32];

    int beg = g_rowstart[n];
    int cnt = g_edeg[n];
    #pragma unroll 4
    for (int j = 0; j < cnt; j++) {
        int s = g_csrc[beg + j];
        float w = g_cw[beg + j];
        a0 += w * g_hw[s * DD + lane];
        a1 += w * g_hw[s * DD + lane + 32];
    }

    float mu = warp_sum(a0 + a1) * (1.0f / DD);
    float d0 = a0 - mu, d1 = a1 - mu;
    float var = warp_sum(d0 * d0 + d1 * d1) * (1.0f / DD);
    float rs = rsqrtf(var + LN_EPS);
    float o0 = fmaxf(d0 * rs * lw[lane]      + lb[lane],      0.0f);
    float o1 = fmaxf(d1 * rs * lw[lane + 32] + lb[lane + 32], 0.0f);
    g_h[n * DD + lane]      = o0;
    g_h[n * DD + lane + 32] = o1;

    if (last) {
        int g = clampi(read_idx(batch, n), NG);
        atomicAdd(&g_pool[g * DD + lane],      o0);
        atomicAdd(&g_pool[g * DD + lane + 32], o1);
    }
}

// ---------------- output projection ------------------------------------------
__global__ void k_final(const float* __restrict__ Wo, const float* __restrict__ bo,
                        float* __restrict__ out) {
    int g = blockIdx.x;
    int j = threadIdx.x;          // 0..31
    float inv = 1.0f / fmaxf(g_cnt[g], 1.0f);
    float acc = bo[j];
    #pragma unroll
    for (int k = 0; k < DD; k++)
        acc += g_pool[g * DD + k] * inv * Wo[k * DOUT + j];
    out[g * DOUT + j] = acc;
}

// ---------------- launch -----------------------------------------------------
extern "C" void kernel_launch(void* const* d_in, const int* in_sizes, int n_in,
                              void* d_out, int out_size) {
    const float* x      = (const float*)d_in[0];
    const void*  ei     = d_in[1];                 // int32 or int64 (probed)
    const void*  batch  = d_in[2];                 // same dtype as ei
    const float* W_in   = (const float*)d_in[3];
    const float* b_in   = (const float*)d_in[4];
    const float* ln_in_w= (const float*)d_in[5];
    const float* ln_in_b= (const float*)d_in[6];
    const float* W_h    = (const float*)d_in[7];   // [2,64,64]
    const float* b_h    = (const float*)d_in[8];   // [2,64]
    const float* ln_h_w = (const float*)d_in[9];   // [2,64]
    const float* ln_h_b = (const float*)d_in[10];  // [2,64]
    const float* W_out  = (const float*)d_in[11];
    const float* b_out  = (const float*)d_in[12];
    float* out = (float*)d_out;

    const int T = 256;
    const int nGrid = (NN + T - 1) / T;
    const int eGrid = (NE + T - 1) / T;
    const int pGrid = (NG * DD + T - 1) / T;

    // dtype probe + CSR + norm build (once per call)
    k_detect<<<1, 256>>>((const int*)ei);
    k_prep  <<<(pGrid > nGrid ? pGrid : nGrid), T>>>();
    k_deg   <<<eGrid, T>>>(ei);
    k_dinv  <<<nGrid, T>>>();
    k_scan1 <<<SCAN_GRID, SCAN_B>>>();
    k_scan2 <<<1, SCAN_B>>>();
    k_scan3 <<<nGrid, T>>>();
    k_bucket<<<eGrid, T>>>();
    k_cnt   <<<nGrid, T>>>(batch);

    const int mmGrid = (NN + 31) / 32;
    const int gGrid  = (NN * 32 + T - 1) / T;   // 1 warp/node

    // layer 0
    k_matmul   <<<mmGrid, T>>>(0, x, W_in);
    k_gather_ln<<<gGrid, T>>>(b_in, ln_in_w, ln_in_b, 0, batch);
    // hidden layers (second one is the last -> fold pooling)
    for (int i = 0; i < 2; i++) {
        k_matmul   <<<mmGrid, T>>>(1, nullptr, W_h + i * DD * DD);
        k_gather_ln<<<gGrid, T>>>(b_h + i * DD, ln_h_w + i * DD, ln_h_b + i * DD,
                                  i == 1, batch);
    }
    k_final<<<NG, DOUT>>>(W_out, b_out, out);
}

// round 7
// speedup vs baseline: 1.0619x; 1.0619x over previous
#include <cuda_runtime.h>
#include <cuda_bf16.h>
#include <cuda_fp16.h>
#include <cstdint>

#define NN 50000
#define NE 800000
#define NG 512
#define DD 64
#define DOUT 32
#define LN_EPS 1e-5f
#define SCAN_B 256
#define SCAN_GRID ((NN + SCAN_B - 1) / SCAN_B)   // 196

// ---------------- scratch (static device globals; 16B aligned) --------------
__device__ int g_is64;                           // 1 if index inputs are int64
__device__ __align__(16) int    g_edeg[NN];      // edge in-degree (no self loop)
__device__ __align__(16) float  g_dinv[NN];
__device__ __align__(16) int    g_src[NE];
__device__ __align__(16) int    g_dst[NE];
__device__ __align__(16) int    g_rows[NN];      // per-block exclusive scan
__device__ __align__(16) int    g_bsum[SCAN_B];
__device__ __align__(16) int    g_bscan[SCAN_B];
__device__ __align__(16) int    g_rowstart[NN];  // CSR row offsets
__device__ __align__(16) int    g_cursor[NN];
__device__ __align__(16) int2   g_csr[NE];       // CSR: {src, weight bits} per slot
__device__ __align__(16) float  g_h[NN * DD];    // layer activations (fp32)
__device__ __align__(16) __half g_hw[NN * DD];   // h @ W (fp16 -> halves gather bytes)
__device__ __align__(16) float  g_pool[NG * DD];
__device__ __align__(16) float  g_cnt[NG];

// ---------------- helpers ---------------------------------------------------
__device__ __forceinline__ float warp_sum(float v) {
    #pragma unroll
    for (int o = 16; o > 0; o >>= 1) v += __shfl_xor_sync(0xffffffffu, v, o);
    return v;
}
__device__ __forceinline__ int clampi(int v, int hi) {   // [0, hi)
    return v < 0 ? 0 : (v >= hi ? hi - 1 : v);
}
__device__ __forceinline__ int read_idx(const void* p, int i) {
    if (g_is64) return (int)((const long long*)p)[i];
    return ((const int*)p)[i];
}

// ---------------- dtype probe ------------------------------------------------
// int64 little-endian with values < 2^31 -> all odd int32 words are zero.
__global__ void k_detect(const int* __restrict__ raw) {
    __shared__ int any;
    if (threadIdx.x == 0) any = 0;
    __syncthreads();
    if (raw[2 * threadIdx.x + 1] != 0) atomicOr(&any, 1);
    __syncthreads();
    if (threadIdx.x == 0) g_is64 = (any == 0) ? 1 : 0;
}

// ---------------- setup kernels ---------------------------------------------
__global__ void k_prep() {
    int i = blockIdx.x * blockDim.x + threadIdx.x;
    if (i < NN) g_edeg[i] = 0;
    if (i < NG * DD) g_pool[i] = 0.0f;
    if (i < NG) g_cnt[i] = 0.0f;
}

__global__ void k_deg(const void* __restrict__ ei) {
    int e = blockIdx.x * blockDim.x + threadIdx.x;
    if (e >= NE) return;
    int s = clampi(read_idx(ei, e), NN);
    int d = clampi(read_idx(ei, NE + e), NN);
    g_src[e] = s;
    g_dst[e] = d;
    atomicAdd(&g_edeg[d], 1);
}

// exclusive scan of g_edeg (stage 1) + fused dinv
__global__ void k_scan1() {
    __shared__ int sh[SCAN_B];
    int t = threadIdx.x;
    int i = blockIdx.x * SCAN_B + t;
    int v = (i < NN) ? g_edeg[i] : 0;
    if (i < NN) g_dinv[i] = rsqrtf((float)(v + 1));   // +1 self loop
    sh[t] = v;
    __syncthreads();
    #pragma unroll
    for (int off = 1; off < SCAN_B; off <<= 1) {
        int x = (t >= off) ? sh[t - off] : 0;
        __syncthreads();
        sh[t] += x;
        __syncthreads();
    }
    if (i < NN) g_rows[i] = sh[t] - v;
    if (t == SCAN_B - 1) g_bsum[blockIdx.x] = sh[t];
}

__global__ void k_scan2() {
    __shared__ int sh[SCAN_B];
    int t = threadIdx.x;
    int v = (t < SCAN_GRID) ? g_bsum[t] : 0;
    sh[t] = v;
    __syncthreads();
    #pragma unroll
    for (int off = 1; off < SCAN_B; off <<= 1) {
        int x = (t >= off) ? sh[t - off] : 0;
        __syncthreads();
        sh[t] += x;
        __syncthreads();
    }
    g_bscan[t] = sh[t] - v;
}

// scan stage 3 + fused graph-size histogram
__global__ void k_scan3(const void* __restrict__ batch) {
    int i = blockIdx.x * blockDim.x + threadIdx.x;
    if (i >= NN) return;
    int r = g_rows[i] + g_bscan[i >> 8];
    g_rowstart[i] = r;
    g_cursor[i] = r;
    atomicAdd(&g_cnt[clampi(read_idx(batch, i), NG)], 1.0f);
}

__global__ void k_bucket() {
    int e = blockIdx.x * blockDim.x + threadIdx.x;
    if (e >= NE) return;
    int s = g_src[e];
    int d = g_dst[e];
    float w = g_dinv[s] * g_dinv[d];
    int pos = atomicAdd(&g_cursor[d], 1);
    g_csr[pos] = make_int2(s, __float_as_int(w));
}

// ---------------- GEMM: g_hw = in @ W  (Nx64 @ 64x64), fp16 output ----------
__global__ void k_matmul(int use_h, const float* __restrict__ xin,
                         const float* __restrict__ W) {
    __shared__ float Ws[DD * DD];
    __shared__ float Is[32][DD + 1];
    const float* in = use_h ? g_h : xin;

    int t = threadIdx.x;
    int base = blockIdx.x * 32;

    #pragma unroll
    for (int r = 0; r < 16; r++) Ws[t + 256 * r] = W[t + 256 * r];
    #pragma unroll
    for (int r = 0; r < 8; r++) {
        int idx = t + 256 * r;
        int row = idx >> 6, col = idx & 63;
        int grow = base + row;
        Is[row][col] = (grow < NN) ? in[grow * DD + col] : 0.0f;
    }
    __syncthreads();

    int rg = t >> 4, cg = t & 15;
    int r0 = rg * 2, r1 = r0 + 1;
    int j0 = cg * 4;

    float4 acc0 = make_float4(0.f, 0.f, 0.f, 0.f);
    float4 acc1 = make_float4(0.f, 0.f, 0.f, 0.f);
    #pragma unroll
    for (int k = 0; k < DD; k++) {
        float4 w4 = *reinterpret_cast<const float4*>(&Ws[k * DD + j0]);
        float a0 = Is[r0][k];
        float a1 = Is[r1][k];
        acc0.x += a0 * w4.x; acc0.y += a0 * w4.y; acc0.z += a0 * w4.z; acc0.w += a0 * w4.w;
        acc1.x += a1 * w4.x; acc1.y += a1 * w4.y; acc1.z += a1 * w4.z; acc1.w += a1 * w4.w;
    }
    int grow0 = base + r0, grow1 = base + r1;
    if (grow0 < NN) {
        __half2* p = reinterpret_cast<__half2*>(&g_hw[grow0 * DD + j0]);
        p[0] = __floats2half2_rn(acc0.x, acc0.y);
        p[1] = __floats2half2_rn(acc0.z, acc0.w);
    }
    if (grow1 < NN) {
        __half2* p = reinterpret_cast<__half2*>(&g_hw[grow1 * DD + j0]);
        p[0] = __floats2half2_rn(acc1.x, acc1.y);
        p[1] = __floats2half2_rn(acc1.z, acc1.w);
    }
}

// ---------------- fused gather + bias + LN + ReLU (+ pool on last) ----------
// one warp per node; lane handles cols 2*lane, 2*lane+1 (half2 granularity).
__global__ void k_gather_ln(const float* __restrict__ b,
                            const float* __restrict__ lw,
                            const float* __restrict__ lb,
                            int last, const void* __restrict__ batch) {
    int n = (blockIdx.x * blockDim.x + threadIdx.x) >> 5;
    int lane = threadIdx.x & 31;
    if (n >= NN) return;

    const __half2* hw2 = reinterpret_cast<const __half2*>(g_hw);

    float ws = g_dinv[n]; ws *= ws;
    float2 bb = reinterpret_cast<const float2*>(b)[lane];
    float2 self = __half22float2(hw2[n * 32 + lane]);
    float a0 = bb.x + ws * self.x;
    float a1 = bb.y + ws * self.y;

    int beg = g_rowstart[n];
    int cnt = g_edeg[n];
    #pragma unroll 4
    for (int j = 0; j < cnt; j++) {
        int2 sw = g_csr[beg + j];
        float w = __int_as_float(sw.y);
        float2 v = __half22float2(hw2[sw.x * 32 + lane]);
        a0 += w * v.x;
        a1 += w * v.y;
    }

    float mu = warp_sum(a0 + a1) * (1.0f / DD);
    float d0 = a0 - mu, d1 = a1 - mu;
    float var = warp_sum(d0 * d0 + d1 * d1) * (1.0f / DD);
    float rs = rsqrtf(var + LN_EPS);
    float2 w2 = reinterpret_cast<const float2*>(lw)[lane];
    float2 lb2 = reinterpret_cast<const float2*>(lb)[lane];
    float o0 = fmaxf(d0 * rs * w2.x + lb2.x, 0.0f);
    float o1 = fmaxf(d1 * rs * w2.y + lb2.y, 0.0f);
    reinterpret_cast<float2*>(g_h)[n * 32 + lane] = make_float2(o0, o1);

    if (last) {
        int g = clampi(read_idx(batch, n), NG);
        atomicAdd(&g_pool[g * DD + 2 * lane],     o0);
        atomicAdd(&g_pool[g * DD + 2 * lane + 1], o1);
    }
}

// ---------------- output projection ------------------------------------------
__global__ void k_final(const float* __restrict__ Wo, const float* __restrict__ bo,
                        float* __restrict__ out) {
    int g = blockIdx.x;
    int j = threadIdx.x;          // 0..31
    float inv = 1.0f / fmaxf(g_cnt[g], 1.0f);
    float acc = bo[j];
    #pragma unroll
    for (int k = 0; k < DD; k++)
        acc += g_pool[g * DD + k] * inv * Wo[k * DOUT + j];
    out[g * DOUT + j] = acc;
}

// ---------------- launch -----------------------------------------------------
extern "C" void kernel_launch(void* const* d_in, const int* in_sizes, int n_in,
                              void* d_out, int out_size) {
    const float* x      = (const float*)d_in[0];
    const void*  ei     = d_in[1];                 // int32 or int64 (probed)
    const void*  batch  = d_in[2];
    const float* W_in   = (const float*)d_in[3];
    const float* b_in   = (const float*)d_in[4];
    const float* ln_in_w= (const float*)d_in[5];
    const float* ln_in_b= (const float*)d_in[6];
    const float* W_h    = (const float*)d_in[7];   // [2,64,64]
    const float* b_h    = (const float*)d_in[8];   // [2,64]
    const float* ln_h_w = (const float*)d_in[9];   // [2,64]
    const float* ln_h_b = (const float*)d_in[10];  // [2,64]
    const float* W_out  = (const float*)d_in[11];
    const float* b_out  = (const float*)d_in[12];
    float* out = (float*)d_out;

    const int T = 256;
    const int nGrid = (NN + T - 1) / T;
    const int eGrid = (NE + T - 1) / T;
    const int pGrid = (NG * DD + T - 1) / T;

    // dtype probe + CSR + norm build (once per call)
    k_detect<<<1, 256>>>((const int*)ei);
    k_prep  <<<(pGrid > nGrid ? pGrid : nGrid), T>>>();
    k_deg   <<<eGrid, T>>>(ei);
    k_scan1 <<<SCAN_GRID, SCAN_B>>>();
    k_scan2 <<<1, SCAN_B>>>();
    k_scan3 <<<nGrid, T>>>(batch);
    k_bucket<<<eGrid, T>>>();

    const int mmGrid = (NN + 31) / 32;
    const int gGrid  = (NN * 32 + T - 1) / T;   // 1 warp/node

    // layer 0
    k_matmul   <<<mmGrid, T>>>(0, x, W_in);
    k_gather_ln<<<gGrid, T>>>(b_in, ln_in_w, ln_in_b, 0, batch);
    // hidden layers (second one is the last -> fold pooling)
    for (int i = 0; i < 2; i++) {
        k_matmul   <<<mmGrid, T>>>(1, nullptr, W_h + i * DD * DD);
        k_gather_ln<<<gGrid, T>>>(b_h + i * DD, ln_h_w + i * DD, ln_h_b + i * DD,
                                  i == 1, batch);
    }
    k_final<<<NG, DOUT>>>(W_out, b_out, out);
}

// round 8
// speedup vs baseline: 1.2786x; 1.2040x over previous
#include <cuda_runtime.h>
#include <cuda_bf16.h>
#include <cuda_fp16.h>
#include <mma.h>
#include <cstdint>

using namespace nvcuda;

#define NN 50000
#define NE 800000
#define NG 512
#define DD 64
#define DOUT 32
#define LN_EPS 1e-5f
#define SCAN_B 256
#define SCAN_GRID ((NN + SCAN_B - 1) / SCAN_B)   // 196
#define MM_ROWS 128

// ---------------- scratch (static device globals; 16B aligned) --------------
__device__ int g_is64;                           // 1 if index inputs are int64
__device__ __align__(16) int    g_edeg[NN];      // edge in-degree (no self loop)
__device__ __align__(16) float  g_dinv[NN];
__device__ __align__(16) int    g_src[NE];
__device__ __align__(16) int    g_dst[NE];
__device__ __align__(16) int    g_rows[NN];      // per-block exclusive scan
__device__ __align__(16) int    g_bsum[SCAN_B];
__device__ __align__(16) int    g_bscan[SCAN_B];
__device__ __align__(16) int    g_rowstart[NN];  // CSR row offsets
__device__ __align__(16) int    g_cursor[NN];
__device__ __align__(16) int2   g_csr[NE];       // CSR: {src, weight bits}
__device__ __align__(16) __half g_h[NN * DD];    // layer activations (fp16)
__device__ __align__(16) __half g_hw[NN * DD];   // h @ W (fp16)
__device__ __align__(16) float  g_pool[NG * DD];
__device__ __align__(16) float  g_cnt[NG];

// ---------------- helpers ---------------------------------------------------
__device__ __forceinline__ float warp_sum(float v) {
    #pragma unroll
    for (int o = 16; o > 0; o >>= 1) v += __shfl_xor_sync(0xffffffffu, v, o);
    return v;
}
__device__ __forceinline__ int clampi(int v, int hi) {   // [0, hi)
    return v < 0 ? 0 : (v >= hi ? hi - 1 : v);
}
__device__ __forceinline__ int read_idx(const void* p, int i) {
    if (g_is64) return (int)((const long long*)p)[i];
    return ((const int*)p)[i];
}

// ---------------- setup kernels ---------------------------------------------
// zero counters; block 0 also probes index dtype (int64 LE values < 2^31 ->
// every odd int32 word of the buffer is zero).
__global__ void k_prep(const int* __restrict__ raw) {
    int i = blockIdx.x * blockDim.x + threadIdx.x;
    if (i < NN) g_edeg[i] = 0;
    if (i < NG * DD) g_pool[i] = 0.0f;
    if (i < NG) g_cnt[i] = 0.0f;
    if (blockIdx.x == 0) {
        __shared__ int any;
        if (threadIdx.x == 0) any = 0;
        __syncthreads();
        if (raw[2 * threadIdx.x + 1] != 0) atomicOr(&any, 1);
        __syncthreads();
        if (threadIdx.x == 0) g_is64 = (any == 0) ? 1 : 0;
    }
}

__global__ void k_deg(const void* __restrict__ ei) {
    int e = blockIdx.x * blockDim.x + threadIdx.x;
    if (e >= NE) return;
    int s = clampi(read_idx(ei, e), NN);
    int d = clampi(read_idx(ei, NE + e), NN);
    g_src[e] = s;
    g_dst[e] = d;
    atomicAdd(&g_edeg[d], 1);
}

// exclusive scan of g_edeg (stage 1) + fused dinv
__global__ void k_scan1() {
    __shared__ int sh[SCAN_B];
    int t = threadIdx.x;
    int i = blockIdx.x * SCAN_B + t;
    int v = (i < NN) ? g_edeg[i] : 0;
    if (i < NN) g_dinv[i] = rsqrtf((float)(v + 1));   // +1 self loop
    sh[t] = v;
    __syncthreads();
    #pragma unroll
    for (int off = 1; off < SCAN_B; off <<= 1) {
        int x = (t >= off) ? sh[t - off] : 0;
        __syncthreads();
        sh[t] += x;
        __syncthreads();
    }
    if (i < NN) g_rows[i] = sh[t] - v;
    if (t == SCAN_B - 1) g_bsum[blockIdx.x] = sh[t];
}

__global__ void k_scan2() {
    __shared__ int sh[SCAN_B];
    int t = threadIdx.x;
    int v = (t < SCAN_GRID) ? g_bsum[t] : 0;
    sh[t] = v;
    __syncthreads();
    #pragma unroll
    for (int off = 1; off < SCAN_B; off <<= 1) {
        int x = (t >= off) ? sh[t - off] : 0;
        __syncthreads();
        sh[t] += x;
        __syncthreads();
    }
    g_bscan[t] = sh[t] - v;
}

// scan stage 3 + fused graph-size histogram
__global__ void k_scan3(const void* __restrict__ batch) {
    int i = blockIdx.x * blockDim.x + threadIdx.x;
    if (i >= NN) return;
    int r = g_rows[i] + g_bscan[i >> 8];
    g_rowstart[i] = r;
    g_cursor[i] = r;
    atomicAdd(&g_cnt[clampi(read_idx(batch, i), NG)], 1.0f);
}

__global__ void k_bucket() {
    int e = blockIdx.x * blockDim.x + threadIdx.x;
    if (e >= NE) return;
    int s = g_src[e];
    int d = g_dst[e];
    float w = g_dinv[s] * g_dinv[d];
    int pos = atomicAdd(&g_cursor[d], 1);
    g_csr[pos] = make_int2(s, __float_as_int(w));
}

// ---------------- GEMM: g_hw = in @ W via wmma (HMMA fp16 -> fp32 acc) ------
// 256 threads, 128 rows/block; 8 warps x (16 rows x 64 cols) output strips.
__global__ void k_matmul(int use_h, const float* __restrict__ xin,
                         const float* __restrict__ W) {
    // As: 128x72 half (18432 B), Bs: 64x72 half (9216 B) -> 27648 B
    // Cs: 128x72 float (36864 B) overlaps As/Bs after the MMA phase.
    __shared__ __align__(16) char sbuf[128 * 72 * 4];
    __half (*As)[72] = reinterpret_cast<__half (*)[72]>(sbuf);
    __half (*Bs)[72] = reinterpret_cast<__half (*)[72]>(sbuf + 128 * 72 * 2);
    float  (*Cs)[72] = reinterpret_cast<float  (*)[72]>(sbuf);

    int t = threadIdx.x;
    int base = blockIdx.x * MM_ROWS;
    int row = t >> 1;                 // 0..127
    int part = (t & 1) * 32;          // 0 or 32
    int grow = base + row;

    // stage A (128 rows x 64 cols, half)
    if (grow < NN) {
        if (use_h) {
            const int4* src = reinterpret_cast<const int4*>(&g_h[grow * DD + part]);
            int4* dst = reinterpret_cast<int4*>(&As[row][part]);
            #pragma unroll
            for (int i = 0; i < 4; i++) dst[i] = src[i];
        } else {
            const float4* src = reinterpret_cast<const float4*>(&xin[grow * DD + part]);
            __half2* dst = reinterpret_cast<__half2*>(&As[row][part]);
            #pragma unroll
            for (int i = 0; i < 8; i++) {
                float4 v = src[i];
                dst[2 * i]     = __floats2half2_rn(v.x, v.y);
                dst[2 * i + 1] = __floats2half2_rn(v.z, v.w);
            }
        }
    } else {
        int4 z = make_int4(0, 0, 0, 0);
        int4* dst = reinterpret_cast<int4*>(&As[row][part]);
        #pragma unroll
        for (int i = 0; i < 4; i++) dst[i] = z;
    }

    // stage B = W (64x64, half); threads 0..127
    if (t < 128) {
        int brow = t >> 1;
        int bpart = (t & 1) * 32;
        const float4* src = reinterpret_cast<const float4*>(&W[brow * DD + bpart]);
        __half2* dst = reinterpret_cast<__half2*>(&Bs[brow][bpart]);
        #pragma unroll
        for (int i = 0; i < 8; i++) {
            float4 v = src[i];
            dst[2 * i]     = __floats2half2_rn(v.x, v.y);
            dst[2 * i + 1] = __floats2half2_rn(v.z, v.w);
        }
    }
    __syncthreads();

    // MMA: each warp computes rows [16w, 16w+16) x all 64 cols
    int w = t >> 5;
    wmma::fragment<wmma::accumulator, 16, 16, 16, float> acc[4];
    #pragma unroll
    for (int n = 0; n < 4; n++) wmma::fill_fragment(acc[n], 0.0f);
    #pragma unroll
    for (int k = 0; k < 4; k++) {
        wmma::fragment<wmma::matrix_a, 16, 16, 16, __half, wmma::row_major> af;
        wmma::load_matrix_sync(af, &As[w * 16][k * 16], 72);
        #pragma unroll
        for (int n = 0; n < 4; n++) {
            wmma::fragment<wmma::matrix_b, 16, 16, 16, __half, wmma::row_major> bf;
            wmma::load_matrix_sync(bf, &Bs[k * 16][n * 16], 72);
            wmma::mma_sync(acc[n], af, bf, acc[n]);
        }
    }
    __syncthreads();   // all A/B reads done; safe to overwrite with Cs

    #pragma unroll
    for (int n = 0; n < 4; n++)
        wmma::store_matrix_sync(&Cs[w * 16][n * 16], acc[n], 72, wmma::mem_row_major);
    __syncthreads();

    // write out (convert to half)
    if (grow < NN) {
        __half2* dst = reinterpret_cast<__half2*>(&g_hw[grow * DD + part]);
        #pragma unroll
        for (int i = 0; i < 16; i++)
            dst[i] = __floats2half2_rn(Cs[row][part + 2 * i], Cs[row][part + 2 * i + 1]);
    }
}

// ---------------- fused gather + bias + LN + ReLU (+ pool on last) ----------
// one warp per node; lane handles cols 2*lane, 2*lane+1.
__global__ void k_gather_ln(const float* __restrict__ b,
                            const float* __restrict__ lw,
                            const float* __restrict__ lb,
                            int last, const void* __restrict__ batch) {
    int n = (blockIdx.x * blockDim.x + threadIdx.x) >> 5;
    int lane = threadIdx.x & 31;
    if (n >= NN) return;

    const __half2* hw2 = reinterpret_cast<const __half2*>(g_hw);

    float ws = g_dinv[n]; ws *= ws;
    float2 bb = reinterpret_cast<const float2*>(b)[lane];
    float2 self = __half22float2(hw2[n * 32 + lane]);
    float a0 = bb.x + ws * self.x;
    float a1 = bb.y + ws * self.y;

    int beg = g_rowstart[n];
    int cnt = g_edeg[n];
    #pragma unroll 4
    for (int j = 0; j < cnt; j++) {
        int2 sw = g_csr[beg + j];
        float w = __int_as_float(sw.y);
        float2 v = __half22float2(hw2[sw.x * 32 + lane]);
        a0 += w * v.x;
        a1 += w * v.y;
    }

    float mu = warp_sum(a0 + a1) * (1.0f / DD);
    float d0 = a0 - mu, d1 = a1 - mu;
    float var = warp_sum(d0 * d0 + d1 * d1) * (1.0f / DD);
    float rs = rsqrtf(var + LN_EPS);
    float2 w2 = reinterpret_cast<const float2*>(lw)[lane];
    float2 lb2 = reinterpret_cast<const float2*>(lb)[lane];
    float o0 = fmaxf(d0 * rs * w2.x + lb2.x, 0.0f);
    float o1 = fmaxf(d1 * rs * w2.y + lb2.y, 0.0f);
    reinterpret_cast<__half2*>(g_h)[n * 32 + lane] = __floats2half2_rn(o0, o1);

    if (last) {
        int g = clampi(read_idx(batch, n), NG);
        atomicAdd(&g_pool[g * DD + 2 * lane],     o0);
        atomicAdd(&g_pool[g * DD + 2 * lane + 1], o1);
    }
}

// ---------------- output projection ------------------------------------------
__global__ void k_final(const float* __restrict__ Wo, const float* __restrict__ bo,
                        float* __restrict__ out) {
    int g = blockIdx.x;
    int j = threadIdx.x;          // 0..31
    float inv = 1.0f / fmaxf(g_cnt[g], 1.0f);
    float acc = bo[j];
    #pragma unroll
    for (int k = 0; k < DD; k++)
        acc += g_pool[g * DD + k] * inv * Wo[k * DOUT + j];
    out[g * DOUT + j] = acc;
}

// ---------------- launch -----------------------------------------------------
extern "C" void kernel_launch(void* const* d_in, const int* in_sizes, int n_in,
                              void* d_out, int out_size) {
    const float* x      = (const float*)d_in[0];
    const void*  ei     = d_in[1];                 // int32 or int64 (probed)
    const void*  batch  = d_in[2];
    const float* W_in   = (const float*)d_in[3];
    const float* b_in   = (const float*)d_in[4];
    const float* ln_in_w= (const float*)d_in[5];
    const float* ln_in_b= (const float*)d_in[6];
    const float* W_h    = (const float*)d_in[7];   // [2,64,64]
    const float* b_h    = (const float*)d_in[8];   // [2,64]
    const float* ln_h_w = (const float*)d_in[9];   // [2,64]
    const float* ln_h_b = (const float*)d_in[10];  // [2,64]
    const float* W_out  = (const float*)d_in[11];
    const float* b_out  = (const float*)d_in[12];
    float* out = (float*)d_out;

    const int T = 256;
    const int nGrid = (NN + T - 1) / T;
    const int eGrid = (NE + T - 1) / T;
    const int pGrid = (NG * DD + T - 1) / T;

    // CSR + norm build (once per call); k_prep block 0 probes index dtype
    k_prep  <<<(pGrid > nGrid ? pGrid : nGrid), T>>>((const int*)ei);
    k_deg   <<<eGrid, T>>>(ei);
    k_scan1 <<<SCAN_GRID, SCAN_B>>>();
    k_scan2 <<<1, SCAN_B>>>();
    k_scan3 <<<nGrid, T>>>(batch);
    k_bucket<<<eGrid, T>>>();

    const int mmGrid = (NN + MM_ROWS - 1) / MM_ROWS;   // 391
    const int gGrid  = (NN * 32 + T - 1) / T;          // 1 warp/node

    // layer 0
    k_matmul   <<<mmGrid, T>>>(0, x, W_in);
    k_gather_ln<<<gGrid, T>>>(b_in, ln_in_w, ln_in_b, 0, batch);
    // hidden layers (second one is the last -> fold pooling)
    for (int i = 0; i < 2; i++) {
        k_matmul   <<<mmGrid, T>>>(1, nullptr, W_h + i * DD * DD);
        k_gather_ln<<<gGrid, T>>>(b_h + i * DD, ln_h_w + i * DD, ln_h_b + i * DD,
                                  i == 1, batch);
    }
    k_final<<<NG, DOUT>>>(W_out, b_out, out);
}

// round 9
// speedup vs baseline: 1.2959x; 1.0136x over previous
#include <cuda_runtime.h>
#include <cuda_bf16.h>
#include <cuda_fp16.h>
#include <mma.h>
#include <cstdint>

using namespace nvcuda;

#define NN 50000
#define NE 800000
#define NG 512
#define DD 64
#define DOUT 32
#define LN_EPS 1e-5f
#define MM_ROWS 128

// ---------------- scratch (static device globals; 16B aligned) --------------
__device__ int g_is64;                           // 1 if index inputs are int64
__device__ int g_alloc;                          // CSR allocation cursor
__device__ __align__(16) int    g_edeg[NN];      // edge in-degree (no self loop)
__device__ __align__(16) float  g_dinv[NN];
__device__ __align__(16) int    g_src[NE];
__device__ __align__(16) int    g_dst[NE];
__device__ __align__(16) int    g_rowstart[NN];  // CSR row offsets (unordered alloc)
__device__ __align__(16) int    g_cursor[NN];
__device__ __align__(16) int2   g_csr[NE];       // CSR: {src, weight bits}
__device__ __align__(16) __half g_h[NN * DD];    // layer activations (fp16)
__device__ __align__(16) __half g_hw[NN * DD];   // h @ W (fp16)
__device__ __align__(16) float  g_pool[NG * DD];
__device__ __align__(16) float  g_cnt[NG];

// ---------------- helpers ---------------------------------------------------
__device__ __forceinline__ float warp_sum(float v) {
    #pragma unroll
    for (int o = 16; o > 0; o >>= 1) v += __shfl_xor_sync(0xffffffffu, v, o);
    return v;
}
__device__ __forceinline__ int clampi(int v, int hi) {   // [0, hi)
    return v < 0 ? 0 : (v >= hi ? hi - 1 : v);
}
__device__ __forceinline__ int read_idx(const void* p, int i) {
    if (g_is64) return (int)((const long long*)p)[i];
    return ((const int*)p)[i];
}

// ---------------- setup kernels ---------------------------------------------
// zero edeg/cnt/alloc; block 0 probes index dtype (int64 LE values < 2^31 ->
// every odd int32 word of the buffer is zero).
__global__ void k_prep(const int* __restrict__ raw) {
    int i = blockIdx.x * blockDim.x + threadIdx.x;
    if (i < NN) g_edeg[i] = 0;
    if (i < NG) g_cnt[i] = 0.0f;
    if (i == 0) g_alloc = 0;
    if (blockIdx.x == 0) {
        __shared__ int any;
        if (threadIdx.x == 0) any = 0;
        __syncthreads();
        if (raw[2 * threadIdx.x + 1] != 0) atomicOr(&any, 1);
        __syncthreads();
        if (threadIdx.x == 0) g_is64 = (any == 0) ? 1 : 0;
    }
}

__global__ void k_deg(const void* __restrict__ ei) {
    int e = blockIdx.x * blockDim.x + threadIdx.x;
    if (e >= NE) return;
    int s = clampi(read_idx(ei, e), NN);
    int d = clampi(read_idx(ei, NE + e), NN);
    g_src[e] = s;
    g_dst[e] = d;
    atomicAdd(&g_edeg[d], 1);
}

// CSR slot allocation (order-free) + dinv + pool zero + graph-size histogram.
// Replaces the 3-stage exclusive scan: rows only need contiguity, not order.
__global__ void k_alloc(const void* __restrict__ batch) {
    int i = blockIdx.x * blockDim.x + threadIdx.x;
    if (i < NG * DD) g_pool[i] = 0.0f;
    if (i >= NN) return;
    int d = g_edeg[i];
    g_dinv[i] = rsqrtf((float)(d + 1));   // +1 self loop
    int r = atomicAdd(&g_alloc, d);
    g_rowstart[i] = r;
    g_cursor[i] = r;
    atomicAdd(&g_cnt[clampi(read_idx(batch, i), NG)], 1.0f);
}

__global__ void k_bucket() {
    int e = blockIdx.x * blockDim.x + threadIdx.x;
    if (e >= NE) return;
    int s = g_src[e];
    int d = g_dst[e];
    float w = g_dinv[s] * g_dinv[d];
    int pos = atomicAdd(&g_cursor[d], 1);
    g_csr[pos] = make_int2(s, __float_as_int(w));
}

// ---------------- GEMM: g_hw = in @ W via wmma (HMMA fp16 -> fp32 acc) ------
// 256 threads, 128 rows/block; 8 warps x (16 rows x 64 cols) output strips.
__global__ void k_matmul(int use_h, const float* __restrict__ xin,
                         const float* __restrict__ W) {
    // As: 128x72 half, Bs: 64x72 half; Cs: 128x72 float overlaps after MMA.
    __shared__ __align__(16) char sbuf[128 * 72 * 4];
    __half (*As)[72] = reinterpret_cast<__half (*)[72]>(sbuf);
    __half (*Bs)[72] = reinterpret_cast<__half (*)[72]>(sbuf + 128 * 72 * 2);
    float  (*Cs)[72] = reinterpret_cast<float  (*)[72]>(sbuf);

    int t = threadIdx.x;
    int base = blockIdx.x * MM_ROWS;
    int row = t >> 1;                 // 0..127
    int part = (t & 1) * 32;          // 0 or 32
    int grow = base + row;

    // stage A (128 rows x 64 cols, half)
    if (grow < NN) {
        if (use_h) {
            const int4* src = reinterpret_cast<const int4*>(&g_h[grow * DD + part]);
            int4* dst = reinterpret_cast<int4*>(&As[row][part]);
            #pragma unroll
            for (int i = 0; i < 4; i++) dst[i] = src[i];
        } else {
            const float4* src = reinterpret_cast<const float4*>(&xin[grow * DD + part]);
            __half2* dst = reinterpret_cast<__half2*>(&As[row][part]);
            #pragma unroll
            for (int i = 0; i < 8; i++) {
                float4 v = src[i];
                dst[2 * i]     = __floats2half2_rn(v.x, v.y);
                dst[2 * i + 1] = __floats2half2_rn(v.z, v.w);
            }
        }
    } else {
        int4 z = make_int4(0, 0, 0, 0);
        int4* dst = reinterpret_cast<int4*>(&As[row][part]);
        #pragma unroll
        for (int i = 0; i < 4; i++) dst[i] = z;
    }

    // stage B = W (64x64, half); threads 0..127
    if (t < 128) {
        int brow = t >> 1;
        int bpart = (t & 1) * 32;
        const float4* src = reinterpret_cast<const float4*>(&W[brow * DD + bpart]);
        __half2* dst = reinterpret_cast<__half2*>(&Bs[brow][bpart]);
        #pragma unroll
        for (int i = 0; i < 8; i++) {
            float4 v = src[i];
            dst[2 * i]     = __floats2half2_rn(v.x, v.y);
            dst[2 * i + 1] = __floats2half2_rn(v.z, v.w);
        }
    }
    __syncthreads();

    // MMA: each warp computes rows [16w, 16w+16) x all 64 cols
    int w = t >> 5;
    wmma::fragment<wmma::accumulator, 16, 16, 16, float> acc[4];
    #pragma unroll
    for (int n = 0; n < 4; n++) wmma::fill_fragment(acc[n], 0.0f);
    #pragma unroll
    for (int k = 0; k < 4; k++) {
        wmma::fragment<wmma::matrix_a, 16, 16, 16, __half, wmma::row_major> af;
        wmma::load_matrix_sync(af, &As[w * 16][k * 16], 72);
        #pragma unroll
        for (int n = 0; n < 4; n++) {
            wmma::fragment<wmma::matrix_b, 16, 16, 16, __half, wmma::row_major> bf;
            wmma::load_matrix_sync(bf, &Bs[k * 16][n * 16], 72);
            wmma::mma_sync(acc[n], af, bf, acc[n]);
        }
    }
    __syncthreads();   // all A/B reads done; safe to overwrite with Cs

    #pragma unroll
    for (int n = 0; n < 4; n++)
        wmma::store_matrix_sync(&Cs[w * 16][n * 16], acc[n], 72, wmma::mem_row_major);
    __syncthreads();

    // write out (convert to half)
    if (grow < NN) {
        __half2* dst = reinterpret_cast<__half2*>(&g_hw[grow * DD + part]);
        #pragma unroll
        for (int i = 0; i < 16; i++)
            dst[i] = __floats2half2_rn(Cs[row][part + 2 * i], Cs[row][part + 2 * i + 1]);
    }
}

// ---------------- fused gather + bias + LN + ReLU (+ pool on last) ----------
// one warp per node; lane handles cols 2*lane, 2*lane+1.
__global__ void k_gather_ln(const float* __restrict__ b,
                            const float* __restrict__ lw,
                            const float* __restrict__ lb,
                            int last, const void* __restrict__ batch) {
    int n = (blockIdx.x * blockDim.x + threadIdx.x) >> 5;
    int lane = threadIdx.x & 31;
    if (n >= NN) return;

    const __half2* hw2 = reinterpret_cast<const __half2*>(g_hw);

    float ws = g_dinv[n]; ws *= ws;
    float2 bb = reinterpret_cast<const float2*>(b)[lane];
    float2 self = __half22float2(hw2[n * 32 + lane]);
    float a0 = bb.x + ws * self.x;
    float a1 = bb.y + ws * self.y;

    int beg = g_rowstart[n];
    int cnt = g_edeg[n];
    #pragma unroll 4
    for (int j = 0; j < cnt; j++) {
        int2 sw = g_csr[beg + j];
        float w = __int_as_float(sw.y);
        float2 v = __half22float2(hw2[sw.x * 32 + lane]);
        a0 += w * v.x;
        a1 += w * v.y;
    }

    float mu = warp_sum(a0 + a1) * (1.0f / DD);
    float d0 = a0 - mu, d1 = a1 - mu;
    float var = warp_sum(d0 * d0 + d1 * d1) * (1.0f / DD);
    float rs = rsqrtf(var + LN_EPS);
    float2 w2 = reinterpret_cast<const float2*>(lw)[lane];
    float2 lb2 = reinterpret_cast<const float2*>(lb)[lane];
    float o0 = fmaxf(d0 * rs * w2.x + lb2.x, 0.0f);
    float o1 = fmaxf(d1 * rs * w2.y + lb2.y, 0.0f);
    reinterpret_cast<__half2*>(g_h)[n * 32 + lane] = __floats2half2_rn(o0, o1);

    if (last) {
        int g = clampi(read_idx(batch, n), NG);
        atomicAdd(&g_pool[g * DD + 2 * lane],     o0);
        atomicAdd(&g_pool[g * DD + 2 * lane + 1], o1);
    }
}

// ---------------- output projection ------------------------------------------
__global__ void k_final(const float* __restrict__ Wo, const float* __restrict__ bo,
                        float* __restrict__ out) {
    int g = blockIdx.x;
    int j = threadIdx.x;          // 0..31
    float inv = 1.0f / fmaxf(g_cnt[g], 1.0f);
    float acc = bo[j];
    #pragma unroll
    for (int k = 0; k < DD; k++)
        acc += g_pool[g * DD + k] * inv * Wo[k * DOUT + j];
    out[g * DOUT + j] = acc;
}

// ---------------- launch -----------------------------------------------------
extern "C" void kernel_launch(void* const* d_in, const int* in_sizes, int n_in,
                              void* d_out, int out_size) {
    const float* x      = (const float*)d_in[0];
    const void*  ei     = d_in[1];                 // int32 or int64 (probed)
    const void*  batch  = d_in[2];
    const float* W_in   = (const float*)d_in[3];
    const float* b_in   = (const float*)d_in[4];
    const float* ln_in_w= (const float*)d_in[5];
    const float* ln_in_b= (const float*)d_in[6];
    const float* W_h    = (const float*)d_in[7];   // [2,64,64]
    const float* b_h    = (const float*)d_in[8];   // [2,64]
    const float* ln_h_w = (const float*)d_in[9];   // [2,64]
    const float* ln_h_b = (const float*)d_in[10];  // [2,64]
    const float* W_out  = (const float*)d_in[11];
    const float* b_out  = (const float*)d_in[12];
    float* out = (float*)d_out;

    const int T = 256;
    const int nGrid = (NN + T - 1) / T;
    const int eGrid = (NE + T - 1) / T;

    // CSR + norm build (once per call)
    k_prep  <<<nGrid, T>>>((const int*)ei);
    k_deg   <<<eGrid, T>>>(ei);
    k_alloc <<<nGrid, T>>>(batch);
    k_bucket<<<eGrid, T>>>();

    const int mmGrid = (NN + MM_ROWS - 1) / MM_ROWS;   // 391
    const int gGrid  = (NN * 32 + T - 1) / T;          // 1 warp/node

    // layer 0
    k_matmul   <<<mmGrid, T>>>(0, x, W_in);
    k_gather_ln<<<gGrid, T>>>(b_in, ln_in_w, ln_in_b, 0, batch);
    // hidden layers (second one is the last -> fold pooling)
    for (int i = 0; i < 2; i++) {
        k_matmul   <<<mmGrid, T>>>(1, nullptr, W_h + i * DD * DD);
        k_gather_ln<<<gGrid, T>>>(b_h + i * DD, ln_h_w + i * DD, ln_h_b + i * DD,
                                  i == 1, batch);
    }
    k_final<<<NG, DOUT>>>(W_out, b_out, out);
}